// round 10
// baseline (speedup 1.0000x reference)
#include <cuda_runtime.h>
#include <cstdint>

#define E    512
#define HD   256
#define MTXT 2048
#define MVID 8192
#define NSPLIT 4
#define KSPL  2048

#define BM 128
#define BN 128
#define BK 32
#define SSTR 36    // smem row stride in floats (ldmatrix conflict-free)
#define TSTR 132   // transpose-stage stride: bank = 4*row+col -> conflict-free

// ---------------- device scratch ----------------
__device__ float g_Q[(long long)MTXT * E];
__device__ float g_K[(long long)MVID * E];
__device__ float g_Vt[2ll * HD * MVID];
__device__ float g_Wt[2ll * MTXT * MVID];
__device__ float g_part[(long long)NSPLIT * MTXT * E];

__device__ __forceinline__ float rntf32(float x) {
    uint32_t u; asm("cvt.rna.tf32.f32 %0, %1;" : "=r"(u) : "f"(x));
    return __uint_as_float(u);
}
__device__ __forceinline__ uint32_t smem_u32(const void* p) {
    uint32_t a;
    asm("{ .reg .u64 t; cvta.to.shared.u64 t, %1; cvt.u32.u64 %0, t; }" : "=r"(a) : "l"(p));
    return a;
}
__device__ __forceinline__ void mma_tf32(float* c, const uint32_t* a, const uint32_t* b) {
    asm volatile(
        "mma.sync.aligned.m16n8k8.row.col.f32.tf32.tf32.f32 "
        "{%0,%1,%2,%3}, {%4,%5,%6,%7}, {%8,%9}, {%0,%1,%2,%3};"
        : "+f"(c[0]), "+f"(c[1]), "+f"(c[2]), "+f"(c[3])
        : "r"(a[0]), "r"(a[1]), "r"(a[2]), "r"(a[3]), "r"(b[0]), "r"(b[1]));
}
__device__ __forceinline__ void ldsm_x4(uint32_t* r, uint32_t addr) {
    asm volatile("ldmatrix.sync.aligned.m8n8.x4.shared.b16 {%0,%1,%2,%3}, [%4];"
        : "=r"(r[0]), "=r"(r[1]), "=r"(r[2]), "=r"(r[3]) : "r"(addr));
}
__device__ __forceinline__ void ldsm_x2(uint32_t* r, uint32_t addr) {
    asm volatile("ldmatrix.sync.aligned.m8n8.x2.shared.b16 {%0,%1}, [%2];"
        : "=r"(r[0]), "=r"(r[1]) : "r"(addr));
}

// ---------------------------------------------------------------------------
// tf32 mma.sync GEMM: D[m,n] = sum_k A[m,k] * B[n,k]  (both K-major)
// ROUND: loader applies rna->tf32 + nparts-sum; false = pre-rounded inputs.
// epi: 0 = bias+store (final)            1 = transpose store D[n][m] (rounded)
//      3 = attn scatter (torch reshape)  4 = bias+store rounded (Q/K)
//      5 = fused softmax-over-frames -> Wt[h][bt][av] (rounded, /16, /128)
// epi 1 and 5 use a coalesced smem-staged transpose epilogue.
// ---------------------------------------------------------------------------
template<bool ROUND>
__global__ __launch_bounds__(256, 2) void gemm_mma(
    const float* __restrict__ A, int lda, long long aH, long long aS,
    const float* __restrict__ B, int ldb, long long bH, long long bS,
    const float* __restrict__ bias, float* __restrict__ D,
    int K, int nsplit, int nparts, long long pStride,
    int epi, int ldd, long long dH, float scale)
{
    __shared__ float As[BM * SSTR];
    __shared__ float Bs[BN * SSTR];

    const int tid  = threadIdx.x;
    const int warp = tid >> 5;
    const int lane = tid & 31;
    const int gid  = lane >> 2;
    const int tig  = lane & 3;
    const int wm   = warp & 1;
    const int wn   = warp >> 1;

    const int zh = blockIdx.z / nsplit;
    const int zs = blockIdx.z % nsplit;
    const int m0 = blockIdx.y * BM;
    const int n0 = blockIdx.x * BN;
    const float* Ab = A + zh * aH + zs * aS;
    const float* Bb = B + zh * bH + zs * bS;

    float acc[4][4][4];
#pragma unroll
    for (int i = 0; i < 4; i++)
#pragma unroll
        for (int j = 0; j < 4; j++)
#pragma unroll
            for (int c = 0; c < 4; c++) acc[i][j][c] = 0.0f;

    // ldmatrix per-lane source rows/cols
    const int lrA = ((lane >> 3) & 1) * 8 + (lane & 7);
    const int lcA = (lane >> 4) * 4;
    const int lrB = lane & 7;
    const int lcB = ((lane >> 3) & 1) * 4;
    const uint32_t AsU = smem_u32(As);
    const uint32_t BsU = smem_u32(Bs);
    uint32_t aAddr[4], bAddr[4];
#pragma unroll
    for (int mt = 0; mt < 4; mt++)
        aAddr[mt] = AsU + (uint32_t)(((wm * 64 + mt * 16 + lrA) * SSTR + lcA) * 4);
#pragma unroll
    for (int nt = 0; nt < 4; nt++)
        bAddr[nt] = BsU + (uint32_t)(((wn * 32 + nt * 8 + lrB) * SSTR + lcB) * 4);

    const int lm = tid >> 3;
    const int lk = (tid & 7) << 2;
    const int S = K / BK;

    for (int s = 0; s < S; s++) {
        const int k0 = s * BK;
#pragma unroll
        for (int i = 0; i < 4; i++) {
            const int r = lm + i * 32;
            const float* ap = Ab + (long long)(m0 + r) * lda + k0 + lk;
            float4 v = *(const float4*)ap;
            if (ROUND) {
                for (int p = 1; p < nparts; p++) {
                    float4 w = *(const float4*)(ap + (long long)p * pStride);
                    v.x += w.x; v.y += w.y; v.z += w.z; v.w += w.w;
                }
                v = make_float4(rntf32(v.x), rntf32(v.y), rntf32(v.z), rntf32(v.w));
            }
            *(float4*)&As[r * SSTR + lk] = v;
            float4 u = *(const float4*)(Bb + (long long)(n0 + r) * ldb + k0 + lk);
            if (ROUND)
                u = make_float4(rntf32(u.x), rntf32(u.y), rntf32(u.z), rntf32(u.w));
            *(float4*)&Bs[r * SSTR + lk] = u;
        }
        __syncthreads();

#pragma unroll
        for (int ks = 0; ks < 4; ks++) {
            const uint32_t kb = (uint32_t)(ks * 8 * 4);
            uint32_t af[4][4], bf[4][2];
#pragma unroll
            for (int mt = 0; mt < 4; mt++) ldsm_x4(af[mt], aAddr[mt] + kb);
#pragma unroll
            for (int nt = 0; nt < 4; nt++) ldsm_x2(bf[nt], bAddr[nt] + kb);
#pragma unroll
            for (int mt = 0; mt < 4; mt++)
#pragma unroll
                for (int nt = 0; nt < 4; nt++)
                    mma_tf32(acc[mt][nt], af[mt], bf[nt]);
        }
        __syncthreads();
    }

    // ---------------- epilogues ----------------
    if (epi == 5 || epi == 1) {
        if (epi == 5) {
            // softmax over the 64 frame-rows of this thread's wm-half
            // (one complete video); weights = softmax/128, tf32-rounded in acc.
#pragma unroll
            for (int nt = 0; nt < 4; nt++) {
#pragma unroll
                for (int p = 0; p < 2; p++) {
                    float m = -1e30f;
#pragma unroll
                    for (int mt = 0; mt < 4; mt++)
                        m = fmaxf(m, fmaxf(acc[mt][nt][p], acc[mt][nt][p + 2]));
                    m = fmaxf(m, __shfl_xor_sync(0xffffffffu, m, 4));
                    m = fmaxf(m, __shfl_xor_sync(0xffffffffu, m, 8));
                    m = fmaxf(m, __shfl_xor_sync(0xffffffffu, m, 16));
                    float sum = 0.0f;
#pragma unroll
                    for (int mt = 0; mt < 4; mt++) {
                        float e0 = __expf((acc[mt][nt][p]     - m) * 0.0625f);
                        float e1 = __expf((acc[mt][nt][p + 2] - m) * 0.0625f);
                        acc[mt][nt][p]     = e0;
                        acc[mt][nt][p + 2] = e1;
                        sum += e0 + e1;
                    }
                    sum += __shfl_xor_sync(0xffffffffu, sum, 4);
                    sum += __shfl_xor_sync(0xffffffffu, sum, 8);
                    sum += __shfl_xor_sync(0xffffffffu, sum, 16);
                    const float inv = 1.0f / (128.0f * sum);
#pragma unroll
                    for (int mt = 0; mt < 4; mt++) {
                        acc[mt][nt][p]     = rntf32(acc[mt][nt][p]     * inv);
                        acc[mt][nt][p + 2] = rntf32(acc[mt][nt][p + 2] * inv);
                    }
                }
            }
        } else {
#pragma unroll
            for (int nt = 0; nt < 4; nt++)
#pragma unroll
                for (int c = 0; c < 4; c++)
#pragma unroll
                    for (int mt = 0; mt < 4; mt++)
                        acc[mt][nt][c] = rntf32(acc[mt][nt][c]);
        }

        // smem-staged transpose: per nt-chunk, tile = 128(m) x 32(n-local),
        // then each warp stores full contiguous 512B rows of D[n][m].
        float* Ts = As;   // 32 x TSTR floats = 4224 <= 4608 available
        for (int nt = 0; nt < 4; nt++) {
            __syncthreads();
#pragma unroll
            for (int mt = 0; mt < 4; mt++)
#pragma unroll
                for (int p = 0; p < 2; p++)
#pragma unroll
                    for (int h = 0; h < 2; h++) {
                        int rloc = wn * 8 + 2 * tig + p;
                        int av   = wm * 64 + mt * 16 + gid + 8 * h;
                        Ts[rloc * TSTR + av] = acc[mt][nt][p + 2 * h];
                    }
            __syncthreads();
#pragma unroll
            for (int i = 0; i < 4; i++) {
                int rl = warp + 8 * i;
                int nO = n0 + nt * 8 + (rl >> 3) * 32 + (rl & 7);
                float4 v = *(float4*)&Ts[rl * TSTR + lane * 4];
                *(float4*)&D[(long long)zh * dH + (long long)nO * MVID + m0 + lane * 4] = v;
            }
        }
        return;
    }

#pragma unroll
    for (int mt = 0; mt < 4; mt++) {
#pragma unroll
        for (int nt = 0; nt < 4; nt++) {
            const int r0 = m0 + wm * 64 + mt * 16 + gid;
            const int cN = n0 + wn * 32 + nt * 8 + 2 * tig;
#pragma unroll
            for (int half = 0; half < 2; half++) {
                const int r = r0 + half * 8;
                float x = acc[mt][nt][half * 2 + 0];
                float y = acc[mt][nt][half * 2 + 1];
                if (epi == 0) {
                    float2 o = make_float2(x * scale + bias[cN],
                                           y * scale + bias[cN + 1]);
                    *(float2*)&D[dH * zh + (long long)r * ldd + cN] = o;
                } else if (epi == 4) {
                    float2 o = make_float2(rntf32(x * scale + bias[cN]),
                                           rntf32(y * scale + bias[cN + 1]));
                    *(float2*)&D[dH * zh + (long long)r * ldd + cN] = o;
                } else {
                    // attn scatter: m = b*32+t, n = d (torch reshape layout)
                    long long addr = (long long)zs * pStride
                                   + (long long)(r >> 5) * 16384
                                   + (long long)zh * 8192
                                   + (r & 31) * 256 + cN;
                    *(float2*)&D[addr] = make_float2(x, y);
                }
            }
        }
    }
}

// ---------------------------------------------------------------------------
extern "C" void kernel_launch(void* const* d_in, const int* in_sizes, int n_in,
                              void* d_out, int out_size)
{
    const float* text  = (const float*)d_in[0];
    const float* video = (const float*)d_in[1];
    const float* Wq = (const float*)d_in[2];
    const float* bq = (const float*)d_in[3];
    const float* Wk = (const float*)d_in[4];
    const float* bk = (const float*)d_in[5];
    const float* Wv = (const float*)d_in[6];
    const float* bv = (const float*)d_in[7];
    const float* Wo = (const float*)d_in[8];
    const float* bo = (const float*)d_in[9];
    float* out = (float*)d_out;

    float *Qp, *Kp, *Vtp, *Wtp, *Pp;
    cudaGetSymbolAddress((void**)&Qp,  g_Q);
    cudaGetSymbolAddress((void**)&Kp,  g_K);
    cudaGetSymbolAddress((void**)&Vtp, g_Vt);
    cudaGetSymbolAddress((void**)&Wtp, g_Wt);
    cudaGetSymbolAddress((void**)&Pp,  g_part);

    dim3 t(256);

    // Q/K projections, tf32-rounded outputs (epi4); V with transpose+round (epi1)
    gemm_mma<true><<<dim3(4, 16, 1), t>>>(text, 512, 0, 0,  Wq, 512, 0, 0,
        bq, Qp, 512, 1, 1, 0, 4, 512, 0, 1.0f);
    gemm_mma<true><<<dim3(4, 64, 1), t>>>(video, 512, 0, 0, Wk, 512, 0, 0,
        bk, Kp, 512, 1, 1, 0, 4, 512, 0, 1.0f);
    gemm_mma<true><<<dim3(4, 64, 1), t>>>(video, 512, 0, 0, Wv, 512, 0, 0,
        bv, Vtp, 512, 1, 1, 0, 1, 0, 0, 1.0f);

    // Logits + fused softmax (epi5): writes Wt[h][bt][av] directly, coalesced
    gemm_mma<false><<<dim3(16, 64, 2), t>>>(Kp, 512, 256, 0, Qp, 512, 256, 0,
        nullptr, Wtp, 256, 1, 1, 0, 5, 0, (long long)MTXT * MVID, 1.0f);

    // Attention: D[bt, d] = sum_av Wt[bt,av] * Vt[d,av], split-K x4 (epi3)
    gemm_mma<false><<<dim3(2, 16, 2 * NSPLIT), t>>>(Wtp, MVID, (long long)MTXT * MVID, KSPL,
        Vtp, MVID, (long long)HD * MVID, KSPL,
        nullptr, Pp, KSPL, NSPLIT, 1, (long long)MTXT * E, 3, 0, 0, 1.0f);

    // Output projection, summing the 4 split-K partials during A-load (epi0)
    gemm_mma<true><<<dim3(4, 16, 1), t>>>(Pp, 512, 0, 0, Wo, 512, 0, 0,
        bo, out, 512, 1, NSPLIT, (long long)MTXT * E, 0, 512, 0, 1.0f);
}

// round 11
// speedup vs baseline: 1.0579x; 1.0579x over previous
#include <cuda_runtime.h>
#include <cstdint>

#define E    512
#define HD   256
#define MTXT 2048
#define MVID 8192
#define NSPLIT 4
#define KSPL  2048

#define BM 128
#define BN 128
#define BK 32
#define SSTR 36    // smem row stride in floats (ldmatrix conflict-free)
#define STAGEF ((BM + BN) * SSTR)        // floats per double-buffer stage
#define SMEM_BYTES (2 * STAGEF * 4)      // 73728 B

// ---------------- device scratch ----------------
__device__ float g_Q[(long long)MTXT * E];
__device__ float g_K[(long long)MVID * E];
__device__ float g_Vt[2ll * HD * MVID];
__device__ float g_Wt[2ll * MTXT * MVID];
__device__ float g_part[(long long)NSPLIT * MTXT * E];

__device__ __forceinline__ float rntf32(float x) {
    uint32_t u; asm("cvt.rna.tf32.f32 %0, %1;" : "=r"(u) : "f"(x));
    return __uint_as_float(u);
}
__device__ __forceinline__ uint32_t smem_u32(const void* p) {
    uint32_t a;
    asm("{ .reg .u64 t; cvta.to.shared.u64 t, %1; cvt.u32.u64 %0, t; }" : "=r"(a) : "l"(p));
    return a;
}
__device__ __forceinline__ void mma_tf32(float* c, const uint32_t* a, const uint32_t* b) {
    asm volatile(
        "mma.sync.aligned.m16n8k8.row.col.f32.tf32.tf32.f32 "
        "{%0,%1,%2,%3}, {%4,%5,%6,%7}, {%8,%9}, {%0,%1,%2,%3};"
        : "+f"(c[0]), "+f"(c[1]), "+f"(c[2]), "+f"(c[3])
        : "r"(a[0]), "r"(a[1]), "r"(a[2]), "r"(a[3]), "r"(b[0]), "r"(b[1]));
}
__device__ __forceinline__ void ldsm_x4(uint32_t* r, uint32_t addr) {
    asm volatile("ldmatrix.sync.aligned.m8n8.x4.shared.b16 {%0,%1,%2,%3}, [%4];"
        : "=r"(r[0]), "=r"(r[1]), "=r"(r[2]), "=r"(r[3]) : "r"(addr));
}
__device__ __forceinline__ void ldsm_x2(uint32_t* r, uint32_t addr) {
    asm volatile("ldmatrix.sync.aligned.m8n8.x2.shared.b16 {%0,%1}, [%2];"
        : "=r"(r[0]), "=r"(r[1]) : "r"(addr));
}

// ---------------------------------------------------------------------------
// tf32 mma.sync GEMM: D[m,n] = sum_k A[m,k] * B[n,k]  (both K-major)
// Register-staged double-buffered smem pipeline, one barrier per stage.
// ROUND: loader applies rna->tf32 + nparts-sum; false = pre-rounded inputs.
// epi: 0 = bias+store (final)            1 = Vt transpose store (rounded)
//      3 = attn scatter (torch reshape)  4 = bias+store rounded (Q/K)
//      5 = fused softmax-over-frames -> Wt[h][bt][av] (rounded, /16, /128)
// ---------------------------------------------------------------------------
template<bool ROUND>
__global__ __launch_bounds__(256, 2) void gemm_mma(
    const float* __restrict__ A, int lda, long long aH, long long aS,
    const float* __restrict__ B, int ldb, long long bH, long long bS,
    const float* __restrict__ bias, float* __restrict__ D,
    int K, int nsplit, int nparts, long long pStride,
    int epi, int ldd, long long dH, float scale)
{
    extern __shared__ float smem[];

    const int tid  = threadIdx.x;
    const int warp = tid >> 5;
    const int lane = tid & 31;
    const int gid  = lane >> 2;
    const int tig  = lane & 3;
    const int wm   = warp & 1;
    const int wn   = warp >> 1;

    const int zh = blockIdx.z / nsplit;
    const int zs = blockIdx.z % nsplit;
    const int m0 = blockIdx.y * BM;
    const int n0 = blockIdx.x * BN;
    const float* Ab = A + zh * aH + zs * aS;
    const float* Bb = B + zh * bH + zs * bS;

    float acc[4][4][4];
#pragma unroll
    for (int i = 0; i < 4; i++)
#pragma unroll
        for (int j = 0; j < 4; j++)
#pragma unroll
            for (int c = 0; c < 4; c++) acc[i][j][c] = 0.0f;

    // ldmatrix per-lane source rows/cols (buffer 0 addresses; +stageB for buf1)
    const int lrA = ((lane >> 3) & 1) * 8 + (lane & 7);
    const int lcA = (lane >> 4) * 4;
    const int lrB = lane & 7;
    const int lcB = ((lane >> 3) & 1) * 4;
    const uint32_t baseU  = smem_u32(smem);
    const uint32_t stageB = (uint32_t)(STAGEF * 4);
    uint32_t aAddr[4], bAddr[4];
#pragma unroll
    for (int mt = 0; mt < 4; mt++)
        aAddr[mt] = baseU + (uint32_t)(((wm * 64 + mt * 16 + lrA) * SSTR + lcA) * 4);
#pragma unroll
    for (int nt = 0; nt < 4; nt++)
        bAddr[nt] = baseU + (uint32_t)((BM * SSTR + (wn * 32 + nt * 8 + lrB) * SSTR + lcB) * 4);

    const int lm = tid >> 3;          // 0..31 base load row
    const int lk = (tid & 7) << 2;    // 0..28 load col
    const int S = K / BK;

    float4 ra[4], rb[4];

    auto ldg_stage = [&](int s) {
        const int k0 = s * BK;
#pragma unroll
        for (int i = 0; i < 4; i++) {
            const int r = lm + i * 32;
            const float* ap = Ab + (long long)(m0 + r) * lda + k0 + lk;
            float4 v = *(const float4*)ap;
            if (ROUND) {
                for (int p = 1; p < nparts; p++) {
                    float4 w = *(const float4*)(ap + (long long)p * pStride);
                    v.x += w.x; v.y += w.y; v.z += w.z; v.w += w.w;
                }
                v = make_float4(rntf32(v.x), rntf32(v.y), rntf32(v.z), rntf32(v.w));
            }
            ra[i] = v;
            float4 u = *(const float4*)(Bb + (long long)(n0 + r) * ldb + k0 + lk);
            if (ROUND)
                u = make_float4(rntf32(u.x), rntf32(u.y), rntf32(u.z), rntf32(u.w));
            rb[i] = u;
        }
    };
    auto sts_stage = [&](int bu) {
        float* As = smem + bu * STAGEF;
        float* Bs = As + BM * SSTR;
#pragma unroll
        for (int i = 0; i < 4; i++) {
            const int r = lm + i * 32;
            *(float4*)&As[r * SSTR + lk] = ra[i];
            *(float4*)&Bs[r * SSTR + lk] = rb[i];
        }
    };
    auto compute = [&](int bu) {
        const uint32_t off = bu * stageB;
#pragma unroll
        for (int ks = 0; ks < 4; ks++) {
            const uint32_t kb = (uint32_t)(ks * 8 * 4) + off;
            uint32_t af[4][4], bf[4][2];
#pragma unroll
            for (int mt = 0; mt < 4; mt++) ldsm_x4(af[mt], aAddr[mt] + kb);
#pragma unroll
            for (int nt = 0; nt < 4; nt++) ldsm_x2(bf[nt], bAddr[nt] + kb);
#pragma unroll
            for (int mt = 0; mt < 4; mt++)
#pragma unroll
                for (int nt = 0; nt < 4; nt++)
                    mma_tf32(acc[mt][nt], af[mt], bf[nt]);
        }
    };

    ldg_stage(0);
    sts_stage(0);
    for (int s = 0; s < S; s++) {
        __syncthreads();
        if (s + 1 < S) ldg_stage(s + 1);
        compute(s & 1);
        if (s + 1 < S) sts_stage((s + 1) & 1);
    }

    // ---------------- epilogues (r8-proven direct stores) ----------------
    if (epi == 5) {
        // Fused softmax over the 64 frame-rows of this thread's wm-half
        // (one complete video), transposed store to Wt[h][bt][av].
#pragma unroll
        for (int nt = 0; nt < 4; nt++) {
#pragma unroll
            for (int p = 0; p < 2; p++) {
                float m = -1e30f;
#pragma unroll
                for (int mt = 0; mt < 4; mt++)
                    m = fmaxf(m, fmaxf(acc[mt][nt][p], acc[mt][nt][p + 2]));
                m = fmaxf(m, __shfl_xor_sync(0xffffffffu, m, 4));
                m = fmaxf(m, __shfl_xor_sync(0xffffffffu, m, 8));
                m = fmaxf(m, __shfl_xor_sync(0xffffffffu, m, 16));
                float sum = 0.0f;
#pragma unroll
                for (int mt = 0; mt < 4; mt++) {
                    float e0 = __expf((acc[mt][nt][p]     - m) * 0.0625f);
                    float e1 = __expf((acc[mt][nt][p + 2] - m) * 0.0625f);
                    acc[mt][nt][p]     = e0;
                    acc[mt][nt][p + 2] = e1;
                    sum += e0 + e1;
                }
                sum += __shfl_xor_sync(0xffffffffu, sum, 4);
                sum += __shfl_xor_sync(0xffffffffu, sum, 8);
                sum += __shfl_xor_sync(0xffffffffu, sum, 16);
                const float inv = 1.0f / (128.0f * sum);
                const int bt = n0 + wn * 32 + nt * 8 + 2 * tig + p;
                const int rb2 = m0 + wm * 64 + gid;
                float* Wc = D + (long long)zh * dH + (long long)bt * MVID;
#pragma unroll
                for (int mt = 0; mt < 4; mt++) {
                    Wc[rb2 + mt * 16    ] = rntf32(acc[mt][nt][p]     * inv);
                    Wc[rb2 + mt * 16 + 8] = rntf32(acc[mt][nt][p + 2] * inv);
                }
            }
        }
        return;
    }

#pragma unroll
    for (int mt = 0; mt < 4; mt++) {
#pragma unroll
        for (int nt = 0; nt < 4; nt++) {
            const int r0 = m0 + wm * 64 + mt * 16 + gid;
            const int cN = n0 + wn * 32 + nt * 8 + 2 * tig;
#pragma unroll
            for (int half = 0; half < 2; half++) {
                const int r = r0 + half * 8;
                float x = acc[mt][nt][half * 2 + 0];
                float y = acc[mt][nt][half * 2 + 1];
                if (epi == 0) {
                    float2 o = make_float2(x * scale + bias[cN],
                                           y * scale + bias[cN + 1]);
                    *(float2*)&D[dH * zh + (long long)r * ldd + cN] = o;
                } else if (epi == 4) {
                    float2 o = make_float2(rntf32(x * scale + bias[cN]),
                                           rntf32(y * scale + bias[cN + 1]));
                    *(float2*)&D[dH * zh + (long long)r * ldd + cN] = o;
                } else if (epi == 1) {
                    // Vt: n = h*256 + d  ->  D[(h*HD+d)*MVID + m], rounded
                    D[(long long)(cN    ) * MVID + r] = rntf32(x);
                    D[(long long)(cN + 1) * MVID + r] = rntf32(y);
                } else {
                    // attn scatter: m = b*32+t, n = d (torch reshape layout)
                    long long addr = (long long)zs * pStride
                                   + (long long)(r >> 5) * 16384
                                   + (long long)zh * 8192
                                   + (r & 31) * 256 + cN;
                    *(float2*)&D[addr] = make_float2(x, y);
                }
            }
        }
    }
}

// ---------------------------------------------------------------------------
extern "C" void kernel_launch(void* const* d_in, const int* in_sizes, int n_in,
                              void* d_out, int out_size)
{
    const float* text  = (const float*)d_in[0];
    const float* video = (const float*)d_in[1];
    const float* Wq = (const float*)d_in[2];
    const float* bq = (const float*)d_in[3];
    const float* Wk = (const float*)d_in[4];
    const float* bk = (const float*)d_in[5];
    const float* Wv = (const float*)d_in[6];
    const float* bv = (const float*)d_in[7];
    const float* Wo = (const float*)d_in[8];
    const float* bo = (const float*)d_in[9];
    float* out = (float*)d_out;

    float *Qp, *Kp, *Vtp, *Wtp, *Pp;
    cudaGetSymbolAddress((void**)&Qp,  g_Q);
    cudaGetSymbolAddress((void**)&Kp,  g_K);
    cudaGetSymbolAddress((void**)&Vtp, g_Vt);
    cudaGetSymbolAddress((void**)&Wtp, g_Wt);
    cudaGetSymbolAddress((void**)&Pp,  g_part);

    cudaFuncSetAttribute(gemm_mma<true>,
                         cudaFuncAttributeMaxDynamicSharedMemorySize, SMEM_BYTES);
    cudaFuncSetAttribute(gemm_mma<false>,
                         cudaFuncAttributeMaxDynamicSharedMemorySize, SMEM_BYTES);

    dim3 t(256);

    // Q/K projections, tf32-rounded outputs (epi4); V with transpose+round (epi1)
    gemm_mma<true><<<dim3(4, 16, 1), t, SMEM_BYTES>>>(text, 512, 0, 0,  Wq, 512, 0, 0,
        bq, Qp, 512, 1, 1, 0, 4, 512, 0, 1.0f);
    gemm_mma<true><<<dim3(4, 64, 1), t, SMEM_BYTES>>>(video, 512, 0, 0, Wk, 512, 0, 0,
        bk, Kp, 512, 1, 1, 0, 4, 512, 0, 1.0f);
    gemm_mma<true><<<dim3(4, 64, 1), t, SMEM_BYTES>>>(video, 512, 0, 0, Wv, 512, 0, 0,
        bv, Vtp, 512, 1, 1, 0, 1, 0, 0, 1.0f);

    // Logits + fused softmax (epi5): writes Wt[h][bt][av] directly
    gemm_mma<false><<<dim3(16, 64, 2), t, SMEM_BYTES>>>(Kp, 512, 256, 0, Qp, 512, 256, 0,
        nullptr, Wtp, 256, 1, 1, 0, 5, 0, (long long)MTXT * MVID, 1.0f);

    // Attention: D[bt, d] = sum_av Wt[bt,av] * Vt[d,av], split-K x4 (epi3)
    gemm_mma<false><<<dim3(2, 16, 2 * NSPLIT), t, SMEM_BYTES>>>(Wtp, MVID,
        (long long)MTXT * MVID, KSPL,
        Vtp, MVID, (long long)HD * MVID, KSPL,
        nullptr, Pp, KSPL, NSPLIT, 1, (long long)MTXT * E, 3, 0, 0, 1.0f);

    // Output projection, summing the 4 split-K partials during A-load (epi0)
    gemm_mma<true><<<dim3(4, 16, 1), t, SMEM_BYTES>>>(Pp, 512, 0, 0, Wo, 512, 0, 0,
        bo, out, 512, 1, NSPLIT, (long long)MTXT * E, 0, 512, 0, 1.0f);
}